// round 16
// baseline (speedup 1.0000x reference)
#include <cuda_runtime.h>
#include <cuda_fp16.h>
#include <cstdint>

// Block-diagonal linear: y[n, b*64+j] = sum_{k<64} x[n, b*64+k] * w[b*64+j, b*64+k]
// R16: R14 structure exactly (pure fp16 m16n8k16, ldmatrix A, reg-pinned B,
// double-buffered X, line-minimized LDG/STG via smem C bounce), with MULTI=2
// (grid 4096) to halve CTA granularity and shrink the end-of-kernel drain tail.
// rel_err ~2.9e-4 (tolerance 1e-3).

#define N_FEAT   4096
#define BLK      64
#define NBLK     64
#define TROWS    64
#define MULTI    2
#define THREADS  256
#define XSP      36                 // u32 stride X/W planes (ldmatrix conflict-free)
#define PLANE    (TROWS * XSP)      // 2304 u32 per buffer
#define CSP      68                 // f32 stride of C smem tile (LDS.128 conflict-free)

__device__ __forceinline__ uint32_t pack_h2(float a, float b) {
    __half2 H = __float22half2_rn(make_float2(a, b));
    return *(uint32_t*)&H;
}

__device__ __forceinline__ void mma16816(float c[4],
                                         uint32_t a0, uint32_t a1, uint32_t a2, uint32_t a3,
                                         uint32_t b0, uint32_t b1) {
    asm volatile(
        "mma.sync.aligned.m16n8k16.row.col.f32.f16.f16.f32 "
        "{%0,%1,%2,%3}, {%4,%5,%6,%7}, {%8,%9}, {%0,%1,%2,%3};"
        : "+f"(c[0]), "+f"(c[1]), "+f"(c[2]), "+f"(c[3])
        : "r"(a0), "r"(a1), "r"(a2), "r"(a3), "r"(b0), "r"(b1));
}

__device__ __forceinline__ void ldm_x4(uint32_t& r0, uint32_t& r1, uint32_t& r2, uint32_t& r3,
                                       uint32_t addr) {
    asm volatile("ldmatrix.sync.aligned.m8n8.x4.shared.b16 {%0,%1,%2,%3}, [%4];"
                 : "=r"(r0), "=r"(r1), "=r"(r2), "=r"(r3) : "r"(addr));
}

__global__ __launch_bounds__(THREADS, 3)
void sl_blockdiag_kernel(const float* __restrict__ x,
                         const float* __restrict__ w,
                         float* __restrict__ out) {
    __shared__ uint32_t sX[2][PLANE];          // X double buffer (f16x2 packed)
    __shared__ uint32_t sWp[PLANE];            // W plane
    __shared__ float    sC[TROWS * CSP];       // C staging tile

    const int b  = blockIdx.x % NBLK;
    const int tg = blockIdx.x / NBLK;
    const int tid = threadIdx.x;
    const size_t colbase = (size_t)b * BLK;
    const size_t row0cta = (size_t)tg * (TROWS * MULTI);

    // ---- stage W_b once (fp16 round, packed pairs) ----
    #pragma unroll
    for (int i = tid; i < BLK * 16; i += THREADS) {
        int r = i >> 4, q = i & 15;
        float4 v = *(const float4*)(w + (colbase + r) * N_FEAT + colbase + q * 4);
        sWp[r * XSP + 2 * q]     = pack_h2(v.x, v.y);
        sWp[r * XSP + 2 * q + 1] = pack_h2(v.z, v.w);
    }
    __syncthreads();

    const int wid  = tid >> 5;
    const int lane = tid & 31;
    const int g    = lane >> 2;
    const int tq   = lane & 3;
    const int mg   = wid >> 1;
    const int nh   = wid & 1;
    const int m0   = mg * 16;

    // ---- B fragments -> registers (CTA lifetime) ----
    uint32_t bh[4][4][2];
    #pragma unroll
    for (int nt = 0; nt < 4; nt++) {
        int nrow = (nh * 4 + nt) * 8 + g;
        #pragma unroll
        for (int ks = 0; ks < 4; ks++) {
            int a = nrow * XSP + ks * 8 + tq;
            bh[nt][ks][0] = sWp[a];
            bh[nt][ks][1] = sWp[a + 4];
        }
    }

    // ldmatrix address precompute
    const int lane7 = lane & 7;
    const int mat   = lane >> 3;
    const int arow  = m0 + lane7 + ((mat & 1) << 3);
    const int acolu = (mat >> 1) << 2;
    const uint32_t aoff = (uint32_t)(arow * XSP + acolu) * 4u;
    const uint32_t sb0  = (uint32_t)__cvta_generic_to_shared(&sX[0][0]);
    const uint32_t bufbytes = (uint32_t)PLANE * 4u;

    // staging coords: warp = 2 rows x 16 float4-chunks (4 lines per LDG/STG.128)
    const int xr = tid >> 4;        // base row 0..15
    const int xq = tid & 15;        // float4 chunk within row

    // ---- stage X tile 0 ----
    #pragma unroll
    for (int j = 0; j < 4; j++) {
        int r = xr + 16 * j;
        float4 v = *(const float4*)(x + (row0cta + r) * N_FEAT + colbase + 4 * xq);
        uint32_t* d = &sX[0][r * XSP + 2 * xq];
        d[0] = pack_h2(v.x, v.y);
        d[1] = pack_h2(v.z, v.w);
    }
    __syncthreads();

    #pragma unroll
    for (int t = 0; t < MULTI; t++) {
        // prefetch next tile into registers (same 2-rows-per-warp mapping)
        float4 p[4];
        if (t + 1 < MULTI) {
            const float* base = x + (row0cta + (size_t)(t + 1) * TROWS) * N_FEAT + colbase + 4 * xq;
            #pragma unroll
            for (int j = 0; j < 4; j++)
                p[j] = *(const float4*)(base + (size_t)(xr + 16 * j) * N_FEAT);
        }

        const uint32_t tb = sb0 + (uint32_t)(t & 1) * bufbytes;

        float c[4][4];
        #pragma unroll
        for (int i = 0; i < 4; i++)
            #pragma unroll
            for (int j = 0; j < 4; j++) c[i][j] = 0.f;

        #pragma unroll
        for (int ks = 0; ks < 4; ks++) {
            uint32_t a0, a1, a2, a3;
            ldm_x4(a0, a1, a2, a3, tb + aoff + (uint32_t)(ks * 8) * 4u);
            #pragma unroll
            for (int nt = 0; nt < 4; nt++)
                mma16816(c[nt], a0, a1, a2, a3, bh[nt][ks][0], bh[nt][ks][1]);
        }

        // pack + store next X tile
        if (t + 1 < MULTI) {
            uint32_t* nb = sX[(t + 1) & 1];
            #pragma unroll
            for (int j = 0; j < 4; j++) {
                uint32_t* d = &nb[(xr + 16 * j) * XSP + 2 * xq];
                d[0] = pack_h2(p[j].x, p[j].y);
                d[1] = pack_h2(p[j].z, p[j].w);
            }
        }
        __syncthreads();   // (A) next-X ready; also fences prior tile's C reads

        // ---- epilogue via smem: scatter STS (cheap banks), coalesced STG ----
        {
            const int r0 = m0 + g;
            #pragma unroll
            for (int nt = 0; nt < 4; nt++) {
                int col = nh * 32 + nt * 8 + tq * 2;
                *(float2*)(sC + r0 * CSP + col)       = make_float2(c[nt][0], c[nt][1]);
                *(float2*)(sC + (r0 + 8) * CSP + col) = make_float2(c[nt][2], c[nt][3]);
            }
        }
        __syncthreads();   // (B) C tile complete

        {
            const size_t rowbase = row0cta + (size_t)t * TROWS;
            float* obase = out + rowbase * N_FEAT + colbase + 4 * xq;
            #pragma unroll
            for (int j = 0; j < 4; j++) {
                int r = xr + 16 * j;
                float4 v = *(const float4*)(sC + r * CSP + 4 * xq);
                *(float4*)(obase + (size_t)r * N_FEAT) = v;   // warp: 2 rows x 256B -> 4 lines
            }
        }
    }
}

extern "C" void kernel_launch(void* const* d_in, const int* in_sizes, int n_in,
                              void* d_out, int out_size) {
    const float* x = (const float*)d_in[0];
    const float* w = (const float*)d_in[1];
    float* out = (float*)d_out;

    const int n_rows = in_sizes[0] / N_FEAT;                 // 8192
    const int tile_groups = n_rows / (TROWS * MULTI);        // 64

    dim3 grid(NBLK * tile_groups);                           // 4096 CTAs
    sl_blockdiag_kernel<<<grid, THREADS>>>(x, w, out);
}

// round 17
// speedup vs baseline: 1.1163x; 1.1163x over previous
#include <cuda_runtime.h>
#include <cuda_fp16.h>
#include <cstdint>

// Block-diagonal linear: y[n, b*64+j] = sum_{k<64} x[n, b*64+k] * w[b*64+j, b*64+k]
// R17: R14 structure (pure fp16 m16n8k16, ldmatrix A, double-buffered X,
// line-minimized LDG/STG via smem C bounce, MULTI=4) but B fragments loaded
// per-k-step via ldmatrix.x4 from the W smem plane instead of being pinned in
// 32 registers -> ~55 regs -> 4 CTAs/SM (32 warps) for latency hiding.
// rel_err ~2.9e-4 (tolerance 1e-3).

#define N_FEAT   4096
#define BLK      64
#define NBLK     64
#define TROWS    64
#define MULTI    4
#define THREADS  256
#define XSP      36                 // u32 stride X/W planes (ldmatrix conflict-free)
#define PLANE    (TROWS * XSP)      // 2304 u32 per buffer
#define CSP      68                 // f32 stride of C smem tile (LDS.128 conflict-free)

__device__ __forceinline__ uint32_t pack_h2(float a, float b) {
    __half2 H = __float22half2_rn(make_float2(a, b));
    return *(uint32_t*)&H;
}

__device__ __forceinline__ void mma16816(float c[4],
                                         uint32_t a0, uint32_t a1, uint32_t a2, uint32_t a3,
                                         uint32_t b0, uint32_t b1) {
    asm volatile(
        "mma.sync.aligned.m16n8k16.row.col.f32.f16.f16.f32 "
        "{%0,%1,%2,%3}, {%4,%5,%6,%7}, {%8,%9}, {%0,%1,%2,%3};"
        : "+f"(c[0]), "+f"(c[1]), "+f"(c[2]), "+f"(c[3])
        : "r"(a0), "r"(a1), "r"(a2), "r"(a3), "r"(b0), "r"(b1));
}

__device__ __forceinline__ void ldm_x4(uint32_t& r0, uint32_t& r1, uint32_t& r2, uint32_t& r3,
                                       uint32_t addr) {
    asm volatile("ldmatrix.sync.aligned.m8n8.x4.shared.b16 {%0,%1,%2,%3}, [%4];"
                 : "=r"(r0), "=r"(r1), "=r"(r2), "=r"(r3) : "r"(addr));
}

__global__ __launch_bounds__(THREADS, 4)
void sl_blockdiag_kernel(const float* __restrict__ x,
                         const float* __restrict__ w,
                         float* __restrict__ out) {
    __shared__ uint32_t sX[2][PLANE];          // X double buffer (f16x2 packed)
    __shared__ uint32_t sWp[PLANE];            // W plane
    __shared__ float    sC[TROWS * CSP];       // C staging tile

    const int b  = blockIdx.x % NBLK;
    const int tg = blockIdx.x / NBLK;
    const int tid = threadIdx.x;
    const size_t colbase = (size_t)b * BLK;
    const size_t row0cta = (size_t)tg * (TROWS * MULTI);

    // ---- stage W_b once (fp16 round, packed pairs) ----
    #pragma unroll
    for (int i = tid; i < BLK * 16; i += THREADS) {
        int r = i >> 4, q = i & 15;
        float4 v = *(const float4*)(w + (colbase + r) * N_FEAT + colbase + q * 4);
        sWp[r * XSP + 2 * q]     = pack_h2(v.x, v.y);
        sWp[r * XSP + 2 * q + 1] = pack_h2(v.z, v.w);
    }
    __syncthreads();

    const int wid  = tid >> 5;
    const int lane = tid & 31;
    const int g    = lane >> 2;
    const int tq   = lane & 3;
    const int mg   = wid >> 1;
    const int nh   = wid & 1;
    const int m0   = mg * 16;

    // A-fragment ldmatrix address precompute
    const int lane7 = lane & 7;
    const int mat   = lane >> 3;
    const int arow  = m0 + lane7 + ((mat & 1) << 3);
    const int acolu = (mat >> 1) << 2;
    const uint32_t aoff = (uint32_t)(arow * XSP + acolu) * 4u;
    const uint32_t sb0  = (uint32_t)__cvta_generic_to_shared(&sX[0][0]);
    const uint32_t bufbytes = (uint32_t)PLANE * 4u;

    // B-fragment ldmatrix address precompute:
    // x4 op covers matrices (nt_local, half): mat = lane>>3, nt_local = mat>>1,
    // half = mat&1; row = nh*32 + nt_local*8 + lane7; u32 col = ks*8 + half*4.
    // Output regs: r0=b0(nt0) r1=b1(nt0) r2=b0(nt1) r3=b1(nt1).
    const uint32_t swb = (uint32_t)__cvta_generic_to_shared(sWp);
    const int bnt   = mat >> 1;
    const int bhalf = mat & 1;
    const uint32_t boffA = (uint32_t)(((nh * 32 + bnt * 8 + lane7) * XSP) + bhalf * 4) * 4u;
    const uint32_t boffB = boffA + (uint32_t)(16 * XSP) * 4u;   // nt_local + 2

    // staging coords: warp = 2 rows x 16 float4-chunks (4 lines per LDG/STG.128)
    const int xr = tid >> 4;        // base row 0..15
    const int xq = tid & 15;        // float4 chunk within row

    // ---- stage X tile 0 ----
    #pragma unroll
    for (int j = 0; j < 4; j++) {
        int r = xr + 16 * j;
        float4 v = *(const float4*)(x + (row0cta + r) * N_FEAT + colbase + 4 * xq);
        uint32_t* d = &sX[0][r * XSP + 2 * xq];
        d[0] = pack_h2(v.x, v.y);
        d[1] = pack_h2(v.z, v.w);
    }
    __syncthreads();

    #pragma unroll
    for (int t = 0; t < MULTI; t++) {
        // prefetch next tile into registers (same 2-rows-per-warp mapping)
        float4 p[4];
        if (t + 1 < MULTI) {
            const float* base = x + (row0cta + (size_t)(t + 1) * TROWS) * N_FEAT + colbase + 4 * xq;
            #pragma unroll
            for (int j = 0; j < 4; j++)
                p[j] = *(const float4*)(base + (size_t)(xr + 16 * j) * N_FEAT);
        }

        const uint32_t tb = sb0 + (uint32_t)(t & 1) * bufbytes;

        float c[4][4];
        #pragma unroll
        for (int i = 0; i < 4; i++)
            #pragma unroll
            for (int j = 0; j < 4; j++) c[i][j] = 0.f;

        #pragma unroll
        for (int ks = 0; ks < 4; ks++) {
            const uint32_t kb = (uint32_t)(ks * 8) * 4u;
            uint32_t a0, a1, a2, a3;
            ldm_x4(a0, a1, a2, a3, tb + aoff + kb);
            uint32_t b00, b01, b10, b11;
            ldm_x4(b00, b01, b10, b11, swb + boffA + kb);   // nt 0,1
            uint32_t b20, b21, b30, b31;
            ldm_x4(b20, b21, b30, b31, swb + boffB + kb);   // nt 2,3
            mma16816(c[0], a0, a1, a2, a3, b00, b01);
            mma16816(c[1], a0, a1, a2, a3, b10, b11);
            mma16816(c[2], a0, a1, a2, a3, b20, b21);
            mma16816(c[3], a0, a1, a2, a3, b30, b31);
        }

        // pack + store next X tile
        if (t + 1 < MULTI) {
            uint32_t* nb = sX[(t + 1) & 1];
            #pragma unroll
            for (int j = 0; j < 4; j++) {
                uint32_t* d = &nb[(xr + 16 * j) * XSP + 2 * xq];
                d[0] = pack_h2(p[j].x, p[j].y);
                d[1] = pack_h2(p[j].z, p[j].w);
            }
        }
        __syncthreads();   // (A) next-X ready; also fences prior tile's C reads

        // ---- epilogue via smem: scatter STS (cheap banks), coalesced STG ----
        {
            const int r0 = m0 + g;
            #pragma unroll
            for (int nt = 0; nt < 4; nt++) {
                int col = nh * 32 + nt * 8 + tq * 2;
                *(float2*)(sC + r0 * CSP + col)       = make_float2(c[nt][0], c[nt][1]);
                *(float2*)(sC + (r0 + 8) * CSP + col) = make_float2(c[nt][2], c[nt][3]);
            }
        }
        __syncthreads();   // (B) C tile complete

        {
            const size_t rowbase = row0cta + (size_t)t * TROWS;
            float* obase = out + rowbase * N_FEAT + colbase + 4 * xq;
            #pragma unroll
            for (int j = 0; j < 4; j++) {
                int r = xr + 16 * j;
                float4 v = *(const float4*)(sC + r * CSP + 4 * xq);
                *(float4*)(obase + (size_t)r * N_FEAT) = v;   // warp: 2 rows x 256B -> 4 lines
            }
        }
    }
}

extern "C" void kernel_launch(void* const* d_in, const int* in_sizes, int n_in,
                              void* d_out, int out_size) {
    const float* x = (const float*)d_in[0];
    const float* w = (const float*)d_in[1];
    float* out = (float*)d_out;

    const int n_rows = in_sizes[0] / N_FEAT;                 // 8192
    const int tile_groups = n_rows / (TROWS * MULTI);        // 32

    dim3 grid(NBLK * tile_groups);                           // 2048 CTAs
    sl_blockdiag_kernel<<<grid, THREADS>>>(x, w, out);
}